// round 12
// baseline (speedup 1.0000x reference)
#include <cuda_runtime.h>
#include <cuda_bf16.h>
#include <cstdint>
#include <math.h>

#define BB 4
#define NSEQ 2048
#define CDIM 768
#define HH 12
#define DD 64
#define HIDD 3072
#define MROWS (BB * NSEQ)   // 8192

// ---------------- scratch ----------------
__device__ float g_h[MROWS * CDIM];
__device__ float g_q[MROWS * CDIM];     // fp32 [B,H,N,D], scaled 0.125
__device__ float g_k[MROWS * CDIM];     // fp32 [B,H,N,D]
__device__ float g_v[MROWS * CDIM];     // fp32 [B,H,D,N] d-major
__device__ float g_o[MROWS * CDIM];
__device__ float g_x1[MROWS * CDIM];
__device__ float g_hid[MROWS * HIDD];
// tf32-rounded weights
__device__ float g_wqkv[3 * CDIM * CDIM];
__device__ float g_wproj[CDIM * CDIM];
__device__ float g_wfc1[HIDD * CDIM];
__device__ float g_wfc2[CDIM * HIDD];

__device__ __forceinline__ float to_tf32(float x) {
    float y;
    asm("cvt.rna.tf32.f32 %0, %1;" : "=f"(y) : "f"(x));
    return y;
}
__device__ __forceinline__ uint32_t smem_u32(const void* p) {
    uint32_t a;
    asm("{ .reg .u64 t; cvta.to.shared.u64 t, %1; cvt.u32.u64 %0, t; }" : "=r"(a) : "l"(p));
    return a;
}
__device__ __forceinline__ void mma_tf32(float* d, const uint32_t* a, const uint32_t* b) {
    asm volatile(
        "mma.sync.aligned.m16n8k8.row.col.f32.tf32.tf32.f32 "
        "{%0,%1,%2,%3}, {%4,%5,%6,%7}, {%8,%9}, {%0,%1,%2,%3};"
        : "+f"(d[0]), "+f"(d[1]), "+f"(d[2]), "+f"(d[3])
        : "r"(a[0]), "r"(a[1]), "r"(a[2]), "r"(a[3]), "r"(b[0]), "r"(b[1]));
}
__device__ __forceinline__ void mma_bf16(float* d, const uint32_t* a, uint32_t b0, uint32_t b1) {
    asm volatile(
        "mma.sync.aligned.m16n8k16.row.col.f32.bf16.bf16.f32 "
        "{%0,%1,%2,%3}, {%4,%5,%6,%7}, {%8,%9}, {%0,%1,%2,%3};"
        : "+f"(d[0]), "+f"(d[1]), "+f"(d[2]), "+f"(d[3])
        : "r"(a[0]), "r"(a[1]), "r"(a[2]), "r"(a[3]), "r"(b0), "r"(b1));
}
__device__ __forceinline__ void ldsm4(uint32_t* r, uint32_t addr) {
    asm volatile("ldmatrix.sync.aligned.m8n8.x4.shared.b16 {%0,%1,%2,%3}, [%4];"
                 : "=r"(r[0]), "=r"(r[1]), "=r"(r[2]), "=r"(r[3]) : "r"(addr));
}
__device__ __forceinline__ void cp16(uint32_t dst, const void* src) {
    asm volatile("cp.async.cg.shared.global [%0], [%1], 16;"
                 :: "r"(dst), "l"(__cvta_generic_to_global(src)));
}
#define CP_COMMIT() asm volatile("cp.async.commit_group;" ::: "memory")
#define CP_WAIT1()  asm volatile("cp.async.wait_group 1;" ::: "memory")

__device__ __forceinline__ uint32_t pack_bf16(float a, float b) {
    __nv_bfloat162 h = __floats2bfloat162_rn(a, b);
    return *(uint32_t*)&h;
}

// ---------------- weight tf32 pre-round ----------------
__global__ __launch_bounds__(256) void wcvt_kernel(
    const float* s0, float* d0, int n0, const float* s1, float* d1, int n1,
    const float* s2, float* d2, int n2, const float* s3, float* d3, int n3) {
    const float* s; float* d; int n;
    switch (blockIdx.y) {
        case 0: s = s0; d = d0; n = n0; break;
        case 1: s = s1; d = d1; n = n1; break;
        case 2: s = s2; d = d2; n = n2; break;
        default: s = s3; d = d3; n = n3; break;
    }
    int i = (blockIdx.x * 256 + threadIdx.x) * 4;
    if (i < n) {
        float4 v = *(const float4*)(s + i);
        v.x = to_tf32(v.x); v.y = to_tf32(v.y); v.z = to_tf32(v.z); v.w = to_tf32(v.w);
        *(float4*)(d + i) = v;
    }
}

// ---------------- cp.async tensor-core GEMM: C = A[M,K] * W[Nn,K]^T ----------------
#define GS 3
#define STG_B 32768
#define GEMM_SMEM (GS * STG_B)

template <int EPI>
__global__ __launch_bounds__(256, 2) void gemm_cp(
    const float* __restrict__ A, const float* __restrict__ W,
    const float* __restrict__ bias, const float* __restrict__ res,
    float* __restrict__ C, int M, int Nn, int K,
    float* __restrict__ qout, float* __restrict__ kout, float* __restrict__ vout) {
    extern __shared__ char sm[];
    uint32_t sb = smem_u32(sm);
    int tid = threadIdx.x, lane = tid & 31, wid = tid >> 5;
    int warpM = wid & 1, warpN = wid >> 1;
    int g = lane >> 2, t = lane & 3;
    int rowBase = blockIdx.y * 128, colBase = blockIdx.x * 128;

    float acc[4][4][4];
#pragma unroll
    for (int i = 0; i < 4; i++)
#pragma unroll
        for (int j = 0; j < 4; j++)
#pragma unroll
            for (int e = 0; e < 4; e++) acc[i][j][e] = 0.f;

    const int r0 = tid >> 3;
    const int c16 = tid & 7;
    const uint32_t csw = (uint32_t)((c16 ^ (r0 & 7)) << 4);
    const float* Ab = A + (size_t)rowBase * K + c16 * 4;
    const float* Wb = W + (size_t)colBase * K + c16 * 4;

    const int r7 = lane & 7;
    const int hiA = lane >> 4;
    const int hiB = (lane >> 3) & 1;
    uint32_t rbA[4], rbB[2];
#pragma unroll
    for (int mt = 0; mt < 4; mt++)
        rbA[mt] = (uint32_t)((warpM * 64 + mt * 16 + (lane & 15)) * 128);
#pragma unroll
    for (int p = 0; p < 2; p++)
        rbB[p] = (uint32_t)((warpN * 32 + p * 16 + (lane & 7) + ((lane >> 4) << 3)) * 128) + 16384;

    const int nc = K >> 5;
#pragma unroll
    for (int s = 0; s < GS - 1; s++) {
        uint32_t sA = sb + s * STG_B;
        const float* Ac = Ab + s * 32;
        const float* Wc = Wb + s * 32;
#pragma unroll
        for (int i = 0; i < 4; i++) {
            int r = r0 + i * 32;
            cp16(sA + r * 128 + csw, Ac + (size_t)r * K);
            cp16(sA + 16384 + r * 128 + csw, Wc + (size_t)r * K);
        }
        CP_COMMIT();
    }

    for (int c = 0; c < nc; c++) {
        CP_WAIT1();
        __syncthreads();
        int nxt = c + GS - 1;
        if (nxt < nc) {
            uint32_t sA = sb + (nxt % GS) * STG_B;
            const float* Ac = Ab + nxt * 32;
            const float* Wc = Wb + nxt * 32;
#pragma unroll
            for (int i = 0; i < 4; i++) {
                int r = r0 + i * 32;
                cp16(sA + r * 128 + csw, Ac + (size_t)r * K);
                cp16(sA + 16384 + r * 128 + csw, Wc + (size_t)r * K);
            }
        }
        CP_COMMIT();
        uint32_t stg = sb + (c % GS) * STG_B;
#pragma unroll
        for (int ks = 0; ks < 4; ks++) {
            uint32_t colA = (uint32_t)((((2 * ks + hiA) ^ r7)) << 4);
            uint32_t colB = (uint32_t)((((2 * ks + hiB) ^ r7)) << 4);
            uint32_t af[4][4], bf[2][4];
#pragma unroll
            for (int mt = 0; mt < 4; mt++) ldsm4(af[mt], stg + rbA[mt] + colA);
#pragma unroll
            for (int p = 0; p < 2; p++) ldsm4(bf[p], stg + rbB[p] + colB);
#pragma unroll
            for (int mt = 0; mt < 4; mt++)
#pragma unroll
                for (int nt = 0; nt < 4; nt++)
                    mma_tf32(acc[mt][nt], af[mt], &bf[nt >> 1][(nt & 1) * 2]);
        }
    }

#pragma unroll
    for (int mt = 0; mt < 4; mt++) {
        int rlo = rowBase + warpM * 64 + mt * 16 + g;
#pragma unroll
        for (int nt = 0; nt < 4; nt++) {
            int colb = colBase + warpN * 32 + nt * 8 + t * 2;
#pragma unroll
            for (int half = 0; half < 2; half++) {
                int row = rlo + half * 8;
                float v0 = acc[mt][nt][half * 2 + 0];
                float v1 = acc[mt][nt][half * 2 + 1];
                if (EPI == 0) {
                    int which = colb / CDIM;
                    int rem = colb - which * CDIM;
                    int h = rem >> 6, d0 = rem & 63;
                    int bq = row >> 11, n = row & 2047;
                    if (which == 2) {
                        float* dst = vout + (((size_t)bq * HH + h) * DD + d0) * NSEQ + n;
                        dst[0] = to_tf32(v0);
                        dst[NSEQ] = to_tf32(v1);
                    } else {
                        float scale = (which == 0) ? 0.125f : 1.0f;
                        float* dst = (which == 0 ? qout : kout) +
                                     ((((size_t)bq * HH + h) * NSEQ + n) * DD + d0);
                        *(float2*)dst = make_float2(to_tf32(v0 * scale), to_tf32(v1 * scale));
                    }
                } else if (EPI == 1) {
                    float2 bv = *(const float2*)(bias + colb);
                    float2 rv = *(const float2*)(res + (size_t)row * Nn + colb);
                    *(float2*)(C + (size_t)row * Nn + colb) =
                        make_float2(v0 + bv.x + rv.x, v1 + bv.y + rv.y);
                } else {
                    float2 bv = *(const float2*)(bias + colb);
                    float u0 = v0 + bv.x, u1 = v1 + bv.y;
                    float2 o;
                    o.x = to_tf32(0.5f * u0 * (1.0f + erff(u0 * 0.70710678f)));
                    o.y = to_tf32(0.5f * u1 * (1.0f + erff(u1 * 0.70710678f)));
                    *(float2*)(C + (size_t)row * Nn + colb) = o;
                }
            }
        }
    }
}

// ---------------- LayerNorm (tf32-rounded output) ----------------
__global__ __launch_bounds__(256) void ln_kernel(const float* __restrict__ X,
                                                 const float* __restrict__ gam,
                                                 const float* __restrict__ bet,
                                                 float* __restrict__ out) {
    int row = blockIdx.x;
    const float* xr = X + (size_t)row * CDIM;
    float v[3];
    float s = 0.f, s2 = 0.f;
#pragma unroll
    for (int i = 0; i < 3; i++) {
        v[i] = xr[threadIdx.x + i * 256];
        s += v[i];
        s2 += v[i] * v[i];
    }
#pragma unroll
    for (int o = 16; o > 0; o >>= 1) {
        s  += __shfl_xor_sync(0xffffffffu, s, o);
        s2 += __shfl_xor_sync(0xffffffffu, s2, o);
    }
    __shared__ float ws[8], ws2[8];
    int wid = threadIdx.x >> 5, lane = threadIdx.x & 31;
    if (lane == 0) { ws[wid] = s; ws2[wid] = s2; }
    __syncthreads();
    if (wid == 0) {
        s  = (lane < 8) ? ws[lane] : 0.f;
        s2 = (lane < 8) ? ws2[lane] : 0.f;
#pragma unroll
        for (int o = 4; o > 0; o >>= 1) {
            s  += __shfl_xor_sync(0xffffffffu, s, o);
            s2 += __shfl_xor_sync(0xffffffffu, s2, o);
        }
        if (lane == 0) { ws[0] = s; ws2[0] = s2; }
    }
    __syncthreads();
    float mu   = ws[0] * (1.0f / CDIM);
    float var  = ws2[0] * (1.0f / CDIM) - mu * mu;
    float rstd = rsqrtf(var + 1e-5f);
#pragma unroll
    for (int i = 0; i < 3; i++) {
        int c = threadIdx.x + i * 256;
        out[(size_t)row * CDIM + c] = to_tf32((v[i] - mu) * rstd * gam[c] + bet[c]);
    }
}

// ---------------- Flash attention: bf16 MMA, fp32 inputs converted in-kernel ----------------
// Single K buf 8KB + single V buf 8KB + P 16KB = 32KB. 128B rows, chunk^row&7 swizzle.
#define OFF_KB 0
#define OFF_VB 8192
#define OFF_PB 16384
#define ATT_SMEM 32768
#define L2E 1.44269504f

__global__ __launch_bounds__(256, 2) void attn_mma(const float* __restrict__ Q,
                                                   const float* __restrict__ K,
                                                   const float* __restrict__ V,
                                                   float* __restrict__ O) {
    extern __shared__ float smf[];
    uint32_t sbase = smem_u32(smf);
    int tid = threadIdx.x, lane = tid & 31, wm = tid >> 5;
    int g = lane >> 2, t = lane & 3;
    int bh = blockIdx.y;
    int b = bh / HH, h = bh - b * HH;
    int qbase = blockIdx.x * 128;

    const float* Kbase = K + (size_t)bh * NSEQ * DD;
    const float* Vbase = V + (size_t)bh * DD * NSEQ;   // fp32 d-major

    // Q A-frags: fp32 (scaled 0.125) -> *log2e -> bf16 pack; resident all kernel
    uint32_t qf[4][4];
    {
        const float* Qg = Q + ((size_t)bh * NSEQ + qbase + wm * 16) * DD;
#pragma unroll
        for (int ks = 0; ks < 4; ks++) {
            int c = ks * 16 + 2 * t;
            float2 a0 = *(const float2*)(Qg + (size_t)g * DD + c);
            float2 a1 = *(const float2*)(Qg + (size_t)(g + 8) * DD + c);
            float2 a2 = *(const float2*)(Qg + (size_t)g * DD + c + 8);
            float2 a3 = *(const float2*)(Qg + (size_t)(g + 8) * DD + c + 8);
            qf[ks][0] = pack_bf16(a0.x * L2E, a0.y * L2E);
            qf[ks][1] = pack_bf16(a1.x * L2E, a1.y * L2E);
            qf[ks][2] = pack_bf16(a2.x * L2E, a2.y * L2E);
            qf[ks][3] = pack_bf16(a3.x * L2E, a3.y * L2E);
        }
    }

    float acc_o[8][4];
#pragma unroll
    for (int i = 0; i < 8; i++)
#pragma unroll
        for (int j = 0; j < 4; j++) acc_o[i][j] = 0.f;
    float m0r = -1e30f, m1r = -1e30f, l0 = 0.f, l1 = 0.f;

    const int l15 = lane & 15, l7 = lane & 7, hi = lane >> 4;
    const int str = tid >> 3;       // rows str, str+32
    const int stc = tid & 7;

    // staging destinations (constant: single buffer; (str+32)&7 == str&7)
    char* kdst0 = (char*)smf + OFF_KB + str * 128 + ((stc ^ (str & 7)) << 4);
    char* kdst1 = kdst0 + 32 * 128;
    char* vdst0 = (char*)smf + OFF_VB + str * 128 + ((stc ^ (str & 7)) << 4);
    char* vdst1 = vdst0 + 32 * 128;

    // prologue: stage tile 0 (K + V, fp32 -> bf16)
    {
#pragma unroll
        for (int i = 0; i < 2; i++) {
            int r = str + i * 32;
            const float* ks = Kbase + (size_t)r * DD + stc * 8;
            float4 a = *(const float4*)ks, b2 = *(const float4*)(ks + 4);
            uint4 pk;
            pk.x = pack_bf16(a.x, a.y);  pk.y = pack_bf16(a.z, a.w);
            pk.z = pack_bf16(b2.x, b2.y); pk.w = pack_bf16(b2.z, b2.w);
            *(uint4*)(i ? kdst1 : kdst0) = pk;
            const float* vs = Vbase + (size_t)r * NSEQ + stc * 8;
            float4 va = *(const float4*)vs, vb2 = *(const float4*)(vs + 4);
            uint4 pv;
            pv.x = pack_bf16(va.x, va.y);  pv.y = pack_bf16(va.z, va.w);
            pv.z = pack_bf16(vb2.x, vb2.y); pv.w = pack_bf16(vb2.z, vb2.w);
            *(uint4*)(i ? vdst1 : vdst0) = pv;
        }
        __syncthreads();
    }

    const uint32_t kB = sbase + OFF_KB;
    const uint32_t vB = sbase + OFF_VB;

    for (int kt = 0; kt < NSEQ / 64; kt++) {
        // prefetch + pack next tile into registers (issued before compute)
        uint4 kp0, kp1, vp0, vp1;
        bool has = (kt + 1) < (NSEQ / 64);
        if (has) {
            const float* ksrc = Kbase + (size_t)(kt * 64 + 64 + str) * DD + stc * 8;
            float4 a = *(const float4*)ksrc, b2 = *(const float4*)(ksrc + 4);
            const float* ksrc2 = ksrc + (size_t)32 * DD;
            float4 c = *(const float4*)ksrc2, d = *(const float4*)(ksrc2 + 4);
            const float* vsrc = Vbase + (size_t)str * NSEQ + (kt * 64 + 64) + stc * 8;
            float4 e = *(const float4*)vsrc, f = *(const float4*)(vsrc + 4);
            const float* vsrc2 = vsrc + (size_t)32 * NSEQ;
            float4 gg = *(const float4*)vsrc2, hh = *(const float4*)(vsrc2 + 4);
            kp0.x = pack_bf16(a.x, a.y);  kp0.y = pack_bf16(a.z, a.w);
            kp0.z = pack_bf16(b2.x, b2.y); kp0.w = pack_bf16(b2.z, b2.w);
            kp1.x = pack_bf16(c.x, c.y);  kp1.y = pack_bf16(c.z, c.w);
            kp1.z = pack_bf16(d.x, d.y);  kp1.w = pack_bf16(d.z, d.w);
            vp0.x = pack_bf16(e.x, e.y);  vp0.y = pack_bf16(e.z, e.w);
            vp0.z = pack_bf16(f.x, f.y);  vp0.w = pack_bf16(f.z, f.w);
            vp1.x = pack_bf16(gg.x, gg.y); vp1.y = pack_bf16(gg.z, gg.w);
            vp1.z = pack_bf16(hh.x, hh.y); vp1.w = pack_bf16(hh.z, hh.w);
        }

        // S = Q K^T  (bf16 m16n8k16)
        float s[8][4];
#pragma unroll
        for (int i = 0; i < 8; i++)
#pragma unroll
            for (int j = 0; j < 4; j++) s[i][j] = 0.f;
#pragma unroll
        for (int ks = 0; ks < 4; ks++) {
            uint32_t csw = (uint32_t)(((ks * 2 + hi) ^ l7) << 4);
            uint32_t kb[4][4];
#pragma unroll
            for (int p = 0; p < 4; p++)
                ldsm4(kb[p], kB + (p * 16 + l15) * 128 + csw);
#pragma unroll
            for (int p = 0; p < 4; p++) {
                mma_bf16(s[2 * p + 0], qf[ks], kb[p][0], kb[p][2]);
                mma_bf16(s[2 * p + 1], qf[ks], kb[p][1], kb[p][3]);
            }
        }

        // online softmax (base-2)
        float mx0 = -1e30f, mx1 = -1e30f;
#pragma unroll
        for (int nt = 0; nt < 8; nt++) {
            mx0 = fmaxf(mx0, fmaxf(s[nt][0], s[nt][1]));
            mx1 = fmaxf(mx1, fmaxf(s[nt][2], s[nt][3]));
        }
        mx0 = fmaxf(mx0, __shfl_xor_sync(0xffffffffu, mx0, 1));
        mx0 = fmaxf(mx0, __shfl_xor_sync(0xffffffffu, mx0, 2));
        mx1 = fmaxf(mx1, __shfl_xor_sync(0xffffffffu, mx1, 1));
        mx1 = fmaxf(mx1, __shfl_xor_sync(0xffffffffu, mx1, 2));
        float nm0 = fmaxf(m0r, mx0), nm1 = fmaxf(m1r, mx1);
        float al0 = exp2f(m0r - nm0), al1 = exp2f(m1r - nm1);
        float ts0 = 0.f, ts1 = 0.f;
        char* Pw = (char*)smf + OFF_PB + (wm * 16) * 128;
#pragma unroll
        for (int nt = 0; nt < 8; nt++) {
            float p00 = exp2f(s[nt][0] - nm0);
            float p01 = exp2f(s[nt][1] - nm0);
            float p10 = exp2f(s[nt][2] - nm1);
            float p11 = exp2f(s[nt][3] - nm1);
            ts0 += p00 + p01; ts1 += p10 + p11;
            uint32_t co = (uint32_t)(((nt ^ (g & 7)) << 4) + t * 4);
            *(uint32_t*)(Pw + g * 128 + co) = pack_bf16(p00, p01);
            *(uint32_t*)(Pw + (g + 8) * 128 + co) = pack_bf16(p10, p11);
        }
        ts0 += __shfl_xor_sync(0xffffffffu, ts0, 1);
        ts0 += __shfl_xor_sync(0xffffffffu, ts0, 2);
        ts1 += __shfl_xor_sync(0xffffffffu, ts1, 1);
        ts1 += __shfl_xor_sync(0xffffffffu, ts1, 2);
        l0 = l0 * al0 + ts0;
        l1 = l1 * al1 + ts1;
        m0r = nm0; m1r = nm1;
#pragma unroll
        for (int nt = 0; nt < 8; nt++) {
            acc_o[nt][0] *= al0; acc_o[nt][1] *= al0;
            acc_o[nt][2] *= al1; acc_o[nt][3] *= al1;
        }
        __syncwarp();

        // O += P V  (bf16)
        const uint32_t pAl = sbase + OFF_PB + (wm * 16 + l15) * 128;
#pragma unroll
        for (int kk = 0; kk < 4; kk++) {
            uint32_t csw = (uint32_t)(((kk * 2 + hi) ^ l7) << 4);
            uint32_t pa[4];
            ldsm4(pa, pAl + csw);
#pragma unroll
            for (int p = 0; p < 4; p++) {
                uint32_t vb[4];
                ldsm4(vb, vB + (p * 16 + l15) * 128 + csw);
                mma_bf16(acc_o[2 * p + 0], pa, vb[0], vb[2]);
                mma_bf16(acc_o[2 * p + 1], pa, vb[1], vb[3]);
            }
        }
        __syncthreads();
        if (has) {
            *(uint4*)kdst0 = kp0;
            *(uint4*)kdst1 = kp1;
            *(uint4*)vdst0 = vp0;
            *(uint4*)vdst1 = vp1;
        }
        __syncthreads();
    }

    float inv0 = 1.0f / l0, inv1 = 1.0f / l1;
    int row0 = qbase + wm * 16 + g;
    float* Ob = O + ((size_t)b * NSEQ) * CDIM + h * DD;
#pragma unroll
    for (int nt = 0; nt < 8; nt++) {
        int col = nt * 8 + 2 * t;
        *(float2*)(Ob + (size_t)row0 * CDIM + col) =
            make_float2(to_tf32(acc_o[nt][0] * inv0), to_tf32(acc_o[nt][1] * inv0));
        *(float2*)(Ob + (size_t)(row0 + 8) * CDIM + col) =
            make_float2(to_tf32(acc_o[nt][2] * inv1), to_tf32(acc_o[nt][3] * inv1));
    }
}

// ---------------- host ----------------
extern "C" void kernel_launch(void* const* d_in, const int* in_sizes, int n_in,
                              void* d_out, int out_size) {
    const float* x      = (const float*)d_in[0];
    const float* ln1_g  = (const float*)d_in[1];
    const float* ln1_b  = (const float*)d_in[2];
    const float* qkv_w  = (const float*)d_in[3];
    const float* proj_w = (const float*)d_in[4];
    const float* proj_b = (const float*)d_in[5];
    const float* ln2_g  = (const float*)d_in[6];
    const float* ln2_b  = (const float*)d_in[7];
    const float* fc1_w  = (const float*)d_in[8];
    const float* fc1_b  = (const float*)d_in[9];
    const float* fc2_w  = (const float*)d_in[10];
    const float* fc2_b  = (const float*)d_in[11];
    float* out = (float*)d_out;

    float *h, *q, *k, *v, *o, *x1, *hid, *wqkv, *wproj, *wfc1, *wfc2;
    cudaGetSymbolAddress((void**)&h,    g_h);
    cudaGetSymbolAddress((void**)&q,    g_q);
    cudaGetSymbolAddress((void**)&k,    g_k);
    cudaGetSymbolAddress((void**)&v,    g_v);
    cudaGetSymbolAddress((void**)&o,    g_o);
    cudaGetSymbolAddress((void**)&x1,   g_x1);
    cudaGetSymbolAddress((void**)&hid,  g_hid);
    cudaGetSymbolAddress((void**)&wqkv, g_wqkv);
    cudaGetSymbolAddress((void**)&wproj, g_wproj);
    cudaGetSymbolAddress((void**)&wfc1, g_wfc1);
    cudaGetSymbolAddress((void**)&wfc2, g_wfc2);

    cudaFuncSetAttribute(attn_mma, cudaFuncAttributeMaxDynamicSharedMemorySize, ATT_SMEM);
    cudaFuncSetAttribute(gemm_cp<0>, cudaFuncAttributeMaxDynamicSharedMemorySize, GEMM_SMEM);
    cudaFuncSetAttribute(gemm_cp<1>, cudaFuncAttributeMaxDynamicSharedMemorySize, GEMM_SMEM);
    cudaFuncSetAttribute(gemm_cp<2>, cudaFuncAttributeMaxDynamicSharedMemorySize, GEMM_SMEM);

    int nmax = HIDD * CDIM;
    wcvt_kernel<<<dim3((nmax / 4 + 255) / 256, 4), 256>>>(
        qkv_w, wqkv, 3 * CDIM * CDIM, proj_w, wproj, CDIM * CDIM,
        fc1_w, wfc1, HIDD * CDIM, fc2_w, wfc2, CDIM * HIDD);
    ln_kernel<<<MROWS, 256>>>(x, ln1_g, ln1_b, h);
    gemm_cp<0><<<dim3(3 * CDIM / 128, MROWS / 128), 256, GEMM_SMEM>>>(
        h, wqkv, nullptr, nullptr, nullptr, MROWS, 3 * CDIM, CDIM, q, k, v);
    attn_mma<<<dim3(NSEQ / 128, BB * HH), 256, ATT_SMEM>>>(q, k, v, o);
    gemm_cp<1><<<dim3(CDIM / 128, MROWS / 128), 256, GEMM_SMEM>>>(
        o, wproj, proj_b, x, x1, MROWS, CDIM, CDIM, nullptr, nullptr, nullptr);
    ln_kernel<<<MROWS, 256>>>(x1, ln2_g, ln2_b, h);
    gemm_cp<2><<<dim3(HIDD / 128, MROWS / 128), 256, GEMM_SMEM>>>(
        h, wfc1, fc1_b, nullptr, hid, MROWS, HIDD, CDIM, nullptr, nullptr, nullptr);
    gemm_cp<1><<<dim3(CDIM / 128, MROWS / 128), 256, GEMM_SMEM>>>(
        hid, wfc2, fc2_b, x1, out, MROWS, CDIM, HIDD, nullptr, nullptr, nullptr);
}

// round 14
// speedup vs baseline: 1.0709x; 1.0709x over previous
#include <cuda_runtime.h>
#include <cuda_bf16.h>
#include <cstdint>
#include <math.h>

#define BB 4
#define NSEQ 2048
#define CDIM 768
#define HH 12
#define DD 64
#define HIDD 3072
#define MROWS (BB * NSEQ)   // 8192

// ---------------- scratch ----------------
__device__ float g_h[MROWS * CDIM];
__device__ __nv_bfloat16 g_qb[MROWS * CDIM];   // Q bf16 [B,H,N,D], scaled 0.125*log2e
__device__ __nv_bfloat16 g_kb[MROWS * CDIM];   // K bf16 [B,H,N,D]
__device__ float g_v[MROWS * CDIM];            // V fp32 [B,H,D,N] d-major
__device__ float g_o[MROWS * CDIM];
__device__ float g_x1[MROWS * CDIM];
__device__ float g_hid[MROWS * HIDD];
// tf32-rounded weights
__device__ float g_wqkv[3 * CDIM * CDIM];
__device__ float g_wproj[CDIM * CDIM];
__device__ float g_wfc1[HIDD * CDIM];
__device__ float g_wfc2[CDIM * HIDD];

__device__ __forceinline__ float to_tf32(float x) {
    float y;
    asm("cvt.rna.tf32.f32 %0, %1;" : "=f"(y) : "f"(x));
    return y;
}
__device__ __forceinline__ uint32_t smem_u32(const void* p) {
    uint32_t a;
    asm("{ .reg .u64 t; cvta.to.shared.u64 t, %1; cvt.u32.u64 %0, t; }" : "=r"(a) : "l"(p));
    return a;
}
__device__ __forceinline__ void mma_tf32(float* d, const uint32_t* a, const uint32_t* b) {
    asm volatile(
        "mma.sync.aligned.m16n8k8.row.col.f32.tf32.tf32.f32 "
        "{%0,%1,%2,%3}, {%4,%5,%6,%7}, {%8,%9}, {%0,%1,%2,%3};"
        : "+f"(d[0]), "+f"(d[1]), "+f"(d[2]), "+f"(d[3])
        : "r"(a[0]), "r"(a[1]), "r"(a[2]), "r"(a[3]), "r"(b[0]), "r"(b[1]));
}
__device__ __forceinline__ void mma_bf16(float* d, const uint32_t* a, uint32_t b0, uint32_t b1) {
    asm volatile(
        "mma.sync.aligned.m16n8k16.row.col.f32.bf16.bf16.f32 "
        "{%0,%1,%2,%3}, {%4,%5,%6,%7}, {%8,%9}, {%0,%1,%2,%3};"
        : "+f"(d[0]), "+f"(d[1]), "+f"(d[2]), "+f"(d[3])
        : "r"(a[0]), "r"(a[1]), "r"(a[2]), "r"(a[3]), "r"(b0), "r"(b1));
}
__device__ __forceinline__ void ldsm4(uint32_t* r, uint32_t addr) {
    asm volatile("ldmatrix.sync.aligned.m8n8.x4.shared.b16 {%0,%1,%2,%3}, [%4];"
                 : "=r"(r[0]), "=r"(r[1]), "=r"(r[2]), "=r"(r[3]) : "r"(addr));
}
__device__ __forceinline__ void cp16(uint32_t dst, const void* src) {
    asm volatile("cp.async.cg.shared.global [%0], [%1], 16;"
                 :: "r"(dst), "l"(__cvta_generic_to_global(src)));
}
#define CP_COMMIT() asm volatile("cp.async.commit_group;" ::: "memory")
#define CP_WAIT1()  asm volatile("cp.async.wait_group 1;" ::: "memory")
#define CP_WAIT0()  asm volatile("cp.async.wait_group 0;" ::: "memory")

__device__ __forceinline__ uint32_t pack_bf16(float a, float b) {
    __nv_bfloat162 h = __floats2bfloat162_rn(a, b);
    return *(uint32_t*)&h;
}

// ---------------- weight tf32 pre-round ----------------
__global__ __launch_bounds__(256) void wcvt_kernel(
    const float* s0, float* d0, int n0, const float* s1, float* d1, int n1,
    const float* s2, float* d2, int n2, const float* s3, float* d3, int n3) {
    const float* s; float* d; int n;
    switch (blockIdx.y) {
        case 0: s = s0; d = d0; n = n0; break;
        case 1: s = s1; d = d1; n = n1; break;
        case 2: s = s2; d = d2; n = n2; break;
        default: s = s3; d = d3; n = n3; break;
    }
    int i = (blockIdx.x * 256 + threadIdx.x) * 4;
    if (i < n) {
        float4 v = *(const float4*)(s + i);
        v.x = to_tf32(v.x); v.y = to_tf32(v.y); v.z = to_tf32(v.z); v.w = to_tf32(v.w);
        *(float4*)(d + i) = v;
    }
}

// ---------------- cp.async tensor-core GEMM: C = A[M,K] * W[Nn,K]^T ----------------
#define GS 3
#define STG_B 32768
#define GEMM_SMEM (GS * STG_B)

template <int EPI>
__global__ __launch_bounds__(256, 2) void gemm_cp(
    const float* __restrict__ A, const float* __restrict__ W,
    const float* __restrict__ bias, const float* __restrict__ res,
    float* __restrict__ C, int M, int Nn, int K,
    __nv_bfloat16* __restrict__ qout, __nv_bfloat16* __restrict__ kout,
    float* __restrict__ vout) {
    extern __shared__ char sm[];
    uint32_t sb = smem_u32(sm);
    int tid = threadIdx.x, lane = tid & 31, wid = tid >> 5;
    int warpM = wid & 1, warpN = wid >> 1;
    int g = lane >> 2, t = lane & 3;
    int rowBase = blockIdx.y * 128, colBase = blockIdx.x * 128;

    float acc[4][4][4];
#pragma unroll
    for (int i = 0; i < 4; i++)
#pragma unroll
        for (int j = 0; j < 4; j++)
#pragma unroll
            for (int e = 0; e < 4; e++) acc[i][j][e] = 0.f;

    const int r0 = tid >> 3;
    const int c16 = tid & 7;
    const uint32_t csw = (uint32_t)((c16 ^ (r0 & 7)) << 4);
    const float* Ab = A + (size_t)rowBase * K + c16 * 4;
    const float* Wb = W + (size_t)colBase * K + c16 * 4;

    const int r7 = lane & 7;
    const int hiA = lane >> 4;
    const int hiB = (lane >> 3) & 1;
    uint32_t rbA[4], rbB[2];
#pragma unroll
    for (int mt = 0; mt < 4; mt++)
        rbA[mt] = (uint32_t)((warpM * 64 + mt * 16 + (lane & 15)) * 128);
#pragma unroll
    for (int p = 0; p < 2; p++)
        rbB[p] = (uint32_t)((warpN * 32 + p * 16 + (lane & 7) + ((lane >> 4) << 3)) * 128) + 16384;

    const int nc = K >> 5;
#pragma unroll
    for (int s = 0; s < GS - 1; s++) {
        uint32_t sA = sb + s * STG_B;
        const float* Ac = Ab + s * 32;
        const float* Wc = Wb + s * 32;
#pragma unroll
        for (int i = 0; i < 4; i++) {
            int r = r0 + i * 32;
            cp16(sA + r * 128 + csw, Ac + (size_t)r * K);
            cp16(sA + 16384 + r * 128 + csw, Wc + (size_t)r * K);
        }
        CP_COMMIT();
    }

    for (int c = 0; c < nc; c++) {
        CP_WAIT1();
        __syncthreads();
        int nxt = c + GS - 1;
        if (nxt < nc) {
            uint32_t sA = sb + (nxt % GS) * STG_B;
            const float* Ac = Ab + nxt * 32;
            const float* Wc = Wb + nxt * 32;
#pragma unroll
            for (int i = 0; i < 4; i++) {
                int r = r0 + i * 32;
                cp16(sA + r * 128 + csw, Ac + (size_t)r * K);
                cp16(sA + 16384 + r * 128 + csw, Wc + (size_t)r * K);
            }
        }
        CP_COMMIT();
        uint32_t stg = sb + (c % GS) * STG_B;
#pragma unroll
        for (int ks = 0; ks < 4; ks++) {
            uint32_t colA = (uint32_t)((((2 * ks + hiA) ^ r7)) << 4);
            uint32_t colB = (uint32_t)((((2 * ks + hiB) ^ r7)) << 4);
            uint32_t af[4][4], bf[2][4];
#pragma unroll
            for (int mt = 0; mt < 4; mt++) ldsm4(af[mt], stg + rbA[mt] + colA);
#pragma unroll
            for (int p = 0; p < 2; p++) ldsm4(bf[p], stg + rbB[p] + colB);
#pragma unroll
            for (int mt = 0; mt < 4; mt++)
#pragma unroll
                for (int nt = 0; nt < 4; nt++)
                    mma_tf32(acc[mt][nt], af[mt], &bf[nt >> 1][(nt & 1) * 2]);
        }
    }

#pragma unroll
    for (int mt = 0; mt < 4; mt++) {
        int rlo = rowBase + warpM * 64 + mt * 16 + g;
#pragma unroll
        for (int nt = 0; nt < 4; nt++) {
            int colb = colBase + warpN * 32 + nt * 8 + t * 2;
#pragma unroll
            for (int half = 0; half < 2; half++) {
                int row = rlo + half * 8;
                float v0 = acc[mt][nt][half * 2 + 0];
                float v1 = acc[mt][nt][half * 2 + 1];
                if (EPI == 0) {
                    int which = colb / CDIM;
                    int rem = colb - which * CDIM;
                    int h = rem >> 6, d0 = rem & 63;
                    int bq = row >> 11, n = row & 2047;
                    if (which == 2) {
                        float* dst = vout + (((size_t)bq * HH + h) * DD + d0) * NSEQ + n;
                        dst[0] = v0;
                        dst[NSEQ] = v1;
                    } else {
                        // q scaled by 0.125*log2(e) for exp2 softmax; k unscaled
                        float scale = (which == 0) ? 0.18033688f : 1.0f;
                        __nv_bfloat16* dst = (which == 0 ? qout : kout) +
                                             ((((size_t)bq * HH + h) * NSEQ + n) * DD + d0);
                        *(uint32_t*)dst = pack_bf16(v0 * scale, v1 * scale);
                    }
                } else if (EPI == 1) {
                    float2 bv = *(const float2*)(bias + colb);
                    float2 rv = *(const float2*)(res + (size_t)row * Nn + colb);
                    *(float2*)(C + (size_t)row * Nn + colb) =
                        make_float2(v0 + bv.x + rv.x, v1 + bv.y + rv.y);
                } else {
                    float2 bv = *(const float2*)(bias + colb);
                    float u0 = v0 + bv.x, u1 = v1 + bv.y;
                    float2 o;
                    o.x = to_tf32(0.5f * u0 * (1.0f + erff(u0 * 0.70710678f)));
                    o.y = to_tf32(0.5f * u1 * (1.0f + erff(u1 * 0.70710678f)));
                    *(float2*)(C + (size_t)row * Nn + colb) = o;
                }
            }
        }
    }
}

// ---------------- LayerNorm (tf32-rounded output) ----------------
__global__ __launch_bounds__(256) void ln_kernel(const float* __restrict__ X,
                                                 const float* __restrict__ gam,
                                                 const float* __restrict__ bet,
                                                 float* __restrict__ out) {
    int row = blockIdx.x;
    const float* xr = X + (size_t)row * CDIM;
    float v[3];
    float s = 0.f, s2 = 0.f;
#pragma unroll
    for (int i = 0; i < 3; i++) {
        v[i] = xr[threadIdx.x + i * 256];
        s += v[i];
        s2 += v[i] * v[i];
    }
#pragma unroll
    for (int o = 16; o > 0; o >>= 1) {
        s  += __shfl_xor_sync(0xffffffffu, s, o);
        s2 += __shfl_xor_sync(0xffffffffu, s2, o);
    }
    __shared__ float ws[8], ws2[8];
    int wid = threadIdx.x >> 5, lane = threadIdx.x & 31;
    if (lane == 0) { ws[wid] = s; ws2[wid] = s2; }
    __syncthreads();
    if (wid == 0) {
        s  = (lane < 8) ? ws[lane] : 0.f;
        s2 = (lane < 8) ? ws2[lane] : 0.f;
#pragma unroll
        for (int o = 4; o > 0; o >>= 1) {
            s  += __shfl_xor_sync(0xffffffffu, s, o);
            s2 += __shfl_xor_sync(0xffffffffu, s2, o);
        }
        if (lane == 0) { ws[0] = s; ws2[0] = s2; }
    }
    __syncthreads();
    float mu   = ws[0] * (1.0f / CDIM);
    float var  = ws2[0] * (1.0f / CDIM) - mu * mu;
    float rstd = rsqrtf(var + 1e-5f);
#pragma unroll
    for (int i = 0; i < 3; i++) {
        int c = threadIdx.x + i * 256;
        out[(size_t)row * CDIM + c] = to_tf32((v[i] - mu) * rstd * gam[c] + bet[c]);
    }
}

// ---------------- Flash attention: bf16 MMA, P kept in registers ----------------
// K bf16 2 bufs (cp.async), V bf16 2 bufs (fp32->bf16 during staging). 32KB smem.
// 128B rows, chunk ^= row&7 swizzle.
#define OFF_KB 0
#define OFF_VB 16384
#define ATT_SMEM 32768

__global__ __launch_bounds__(256, 2) void attn_mma(const __nv_bfloat16* __restrict__ Q,
                                                   const __nv_bfloat16* __restrict__ K,
                                                   const float* __restrict__ V,
                                                   float* __restrict__ O) {
    extern __shared__ float smf[];
    uint32_t sbase = smem_u32(smf);
    int tid = threadIdx.x, lane = tid & 31, wm = tid >> 5;
    int g = lane >> 2, t = lane & 3;
    int bh = blockIdx.y;
    int b = bh / HH, h = bh - b * HH;
    int qbase = blockIdx.x * 128;

    const __nv_bfloat16* Kbase = K + (size_t)bh * NSEQ * DD;
    const float* Vbase = V + (size_t)bh * DD * NSEQ;   // fp32 d-major

    // Q A-frags (bf16), resident for whole kernel
    uint32_t qf[4][4];
    {
        const __nv_bfloat16* Qg = Q + ((size_t)bh * NSEQ + qbase + wm * 16) * DD;
#pragma unroll
        for (int ks = 0; ks < 4; ks++) {
            qf[ks][0] = *(const uint32_t*)(Qg + (size_t)g * DD + ks * 16 + 2 * t);
            qf[ks][1] = *(const uint32_t*)(Qg + (size_t)(g + 8) * DD + ks * 16 + 2 * t);
            qf[ks][2] = *(const uint32_t*)(Qg + (size_t)g * DD + ks * 16 + 2 * t + 8);
            qf[ks][3] = *(const uint32_t*)(Qg + (size_t)(g + 8) * DD + ks * 16 + 2 * t + 8);
        }
    }

    float acc_o[8][4];
#pragma unroll
    for (int i = 0; i < 8; i++)
#pragma unroll
        for (int j = 0; j < 4; j++) acc_o[i][j] = 0.f;
    float m0r = -1e30f, m1r = -1e30f, l0 = 0.f, l1 = 0.f;

    const int l15 = lane & 15, l7 = lane & 7, hi = lane >> 4;
    const int str = tid >> 3;       // rows str, str+32
    const int stc = tid & 7;

    // prologue: cp.async K tile 0 into buffer 0
#pragma unroll
    for (int i = 0; i < 2; i++) {
        int r = str + i * 32;
        cp16(sbase + OFF_KB + r * 128 + ((stc ^ (r & 7)) << 4),
             Kbase + (size_t)r * DD + stc * 8);
    }
    CP_COMMIT();

    for (int kt = 0; kt < NSEQ / 64; kt++) {
        int buf = kt & 1;
        // stage V tile kt (fp32 -> bf16) into V buffer buf
#pragma unroll
        for (int i = 0; i < 2; i++) {
            int r = str + i * 32;                    // d index
            const float* vs = Vbase + (size_t)r * NSEQ + kt * 64 + stc * 8;
            float4 a = *(const float4*)(vs);
            float4 bq = *(const float4*)(vs + 4);
            uint4 pk;
            pk.x = pack_bf16(a.x, a.y);  pk.y = pack_bf16(a.z, a.w);
            pk.z = pack_bf16(bq.x, bq.y); pk.w = pack_bf16(bq.z, bq.w);
            *(uint4*)((char*)smf + OFF_VB + buf * 8192 + r * 128 + ((stc ^ (r & 7)) << 4)) = pk;
        }
        CP_WAIT0();
        __syncthreads();
        // issue next K tile
        if (kt + 1 < NSEQ / 64) {
            int nb = buf ^ 1;
#pragma unroll
            for (int i = 0; i < 2; i++) {
                int r = str + i * 32;
                cp16(sbase + OFF_KB + nb * 8192 + r * 128 + ((stc ^ (r & 7)) << 4),
                     Kbase + (size_t)(kt * 64 + 64 + r) * DD + stc * 8);
            }
        }
        CP_COMMIT();

        const uint32_t kB = sbase + OFF_KB + buf * 8192;
        const uint32_t vB = sbase + OFF_VB + buf * 8192;

        // S = Q K^T  (bf16 m16n8k16): 4 ks x 8 nt
        float s[8][4];
#pragma unroll
        for (int i = 0; i < 8; i++)
#pragma unroll
            for (int j = 0; j < 4; j++) s[i][j] = 0.f;
#pragma unroll
        for (int ks = 0; ks < 4; ks++) {
            uint32_t csw = (uint32_t)(((ks * 2 + hi) ^ l7) << 4);
            uint32_t kb[4][4];
#pragma unroll
            for (int p = 0; p < 4; p++)
                ldsm4(kb[p], kB + (p * 16 + l15) * 128 + csw);
#pragma unroll
            for (int p = 0; p < 4; p++) {
                mma_bf16(s[2 * p + 0], qf[ks], kb[p][0], kb[p][2]);
                mma_bf16(s[2 * p + 1], qf[ks], kb[p][1], kb[p][3]);
            }
        }

        // online softmax (base-2); build P A-frags directly in registers
        float mx0 = -1e30f, mx1 = -1e30f;
#pragma unroll
        for (int nt = 0; nt < 8; nt++) {
            mx0 = fmaxf(mx0, fmaxf(s[nt][0], s[nt][1]));
            mx1 = fmaxf(mx1, fmaxf(s[nt][2], s[nt][3]));
        }
        mx0 = fmaxf(mx0, __shfl_xor_sync(0xffffffffu, mx0, 1));
        mx0 = fmaxf(mx0, __shfl_xor_sync(0xffffffffu, mx0, 2));
        mx1 = fmaxf(mx1, __shfl_xor_sync(0xffffffffu, mx1, 1));
        mx1 = fmaxf(mx1, __shfl_xor_sync(0xffffffffu, mx1, 2));
        float nm0 = fmaxf(m0r, mx0), nm1 = fmaxf(m1r, mx1);
        float al0 = exp2f(m0r - nm0), al1 = exp2f(m1r - nm1);
        float ts0 = 0.f, ts1 = 0.f;
        uint32_t pa[4][4];
#pragma unroll
        for (int nt = 0; nt < 8; nt++) {
            float p00 = exp2f(s[nt][0] - nm0);
            float p01 = exp2f(s[nt][1] - nm0);
            float p10 = exp2f(s[nt][2] - nm1);
            float p11 = exp2f(s[nt][3] - nm1);
            ts0 += p00 + p01; ts1 += p10 + p11;
            int kk = nt >> 1, hf = (nt & 1) * 2;
            pa[kk][hf + 0] = pack_bf16(p00, p01);
            pa[kk][hf + 1] = pack_bf16(p10, p11);
        }
        ts0 += __shfl_xor_sync(0xffffffffu, ts0, 1);
        ts0 += __shfl_xor_sync(0xffffffffu, ts0, 2);
        ts1 += __shfl_xor_sync(0xffffffffu, ts1, 1);
        ts1 += __shfl_xor_sync(0xffffffffu, ts1, 2);
        l0 = l0 * al0 + ts0;
        l1 = l1 * al1 + ts1;
        m0r = nm0; m1r = nm1;
#pragma unroll
        for (int nt = 0; nt < 8; nt++) {
            acc_o[nt][0] *= al0; acc_o[nt][1] *= al0;
            acc_o[nt][2] *= al1; acc_o[nt][3] *= al1;
        }

        // O += P V  (bf16): P A-frags from registers
#pragma unroll
        for (int kk = 0; kk < 4; kk++) {
            uint32_t csw = (uint32_t)(((kk * 2 + hi) ^ l7) << 4);
#pragma unroll
            for (int p = 0; p < 4; p++) {
                uint32_t vb[4];
                ldsm4(vb, vB + (p * 16 + l15) * 128 + csw);
                mma_bf16(acc_o[2 * p + 0], pa[kk], vb[0], vb[2]);
                mma_bf16(acc_o[2 * p + 1], pa[kk], vb[1], vb[3]);
            }
        }
    }

    float inv0 = 1.0f / l0, inv1 = 1.0f / l1;
    int row0 = qbase + wm * 16 + g;
    float* Ob = O + ((size_t)b * NSEQ) * CDIM + h * DD;
#pragma unroll
    for (int nt = 0; nt < 8; nt++) {
        int col = nt * 8 + 2 * t;
        *(float2*)(Ob + (size_t)row0 * CDIM + col) =
            make_float2(to_tf32(acc_o[nt][0] * inv0), to_tf32(acc_o[nt][1] * inv0));
        *(float2*)(Ob + (size_t)(row0 + 8) * CDIM + col) =
            make_float2(to_tf32(acc_o[nt][2] * inv1), to_tf32(acc_o[nt][3] * inv1));
    }
}

// ---------------- host ----------------
extern "C" void kernel_launch(void* const* d_in, const int* in_sizes, int n_in,
                              void* d_out, int out_size) {
    const float* x      = (const float*)d_in[0];
    const float* ln1_g  = (const float*)d_in[1];
    const float* ln1_b  = (const float*)d_in[2];
    const float* qkv_w  = (const float*)d_in[3];
    const float* proj_w = (const float*)d_in[4];
    const float* proj_b = (const float*)d_in[5];
    const float* ln2_g  = (const float*)d_in[6];
    const float* ln2_b  = (const float*)d_in[7];
    const float* fc1_w  = (const float*)d_in[8];
    const float* fc1_b  = (const float*)d_in[9];
    const float* fc2_w  = (const float*)d_in[10];
    const float* fc2_b  = (const float*)d_in[11];
    float* out = (float*)d_out;

    float *h, *v, *o, *x1, *hid, *wqkv, *wproj, *wfc1, *wfc2;
    __nv_bfloat16 *qb, *kb;
    cudaGetSymbolAddress((void**)&h,    g_h);
    cudaGetSymbolAddress((void**)&qb,   g_qb);
    cudaGetSymbolAddress((void**)&kb,   g_kb);
    cudaGetSymbolAddress((void**)&v,    g_v);
    cudaGetSymbolAddress((void**)&o,    g_o);
    cudaGetSymbolAddress((void**)&x1,   g_x1);
    cudaGetSymbolAddress((void**)&hid,  g_hid);
    cudaGetSymbolAddress((void**)&wqkv, g_wqkv);
    cudaGetSymbolAddress((void**)&wproj, g_wproj);
    cudaGetSymbolAddress((void**)&wfc1, g_wfc1);
    cudaGetSymbolAddress((void**)&wfc2, g_wfc2);

    cudaFuncSetAttribute(attn_mma, cudaFuncAttributeMaxDynamicSharedMemorySize, ATT_SMEM);
    cudaFuncSetAttribute(gemm_cp<0>, cudaFuncAttributeMaxDynamicSharedMemorySize, GEMM_SMEM);
    cudaFuncSetAttribute(gemm_cp<1>, cudaFuncAttributeMaxDynamicSharedMemorySize, GEMM_SMEM);
    cudaFuncSetAttribute(gemm_cp<2>, cudaFuncAttributeMaxDynamicSharedMemorySize, GEMM_SMEM);

    int nmax = HIDD * CDIM;
    wcvt_kernel<<<dim3((nmax / 4 + 255) / 256, 4), 256>>>(
        qkv_w, wqkv, 3 * CDIM * CDIM, proj_w, wproj, CDIM * CDIM,
        fc1_w, wfc1, HIDD * CDIM, fc2_w, wfc2, CDIM * HIDD);
    ln_kernel<<<MROWS, 256>>>(x, ln1_g, ln1_b, h);
    gemm_cp<0><<<dim3(3 * CDIM / 128, MROWS / 128), 256, GEMM_SMEM>>>(
        h, wqkv, nullptr, nullptr, nullptr, MROWS, 3 * CDIM, CDIM, qb, kb, v);
    attn_mma<<<dim3(NSEQ / 128, BB * HH), 256, ATT_SMEM>>>(qb, kb, v, o);
    gemm_cp<1><<<dim3(CDIM / 128, MROWS / 128), 256, GEMM_SMEM>>>(
        o, wproj, proj_b, x, x1, MROWS, CDIM, CDIM, nullptr, nullptr, nullptr);
    ln_kernel<<<MROWS, 256>>>(x1, ln2_g, ln2_b, h);
    gemm_cp<2><<<dim3(HIDD / 128, MROWS / 128), 256, GEMM_SMEM>>>(
        h, wfc1, fc1_b, nullptr, hid, MROWS, HIDD, CDIM, nullptr, nullptr, nullptr);
    gemm_cp<1><<<dim3(CDIM / 128, MROWS / 128), 256, GEMM_SMEM>>>(
        hid, wfc2, fc2_b, x1, out, MROWS, CDIM, HIDD, nullptr, nullptr, nullptr);
}

// round 15
// speedup vs baseline: 1.7083x; 1.5952x over previous
#include <cuda_runtime.h>
#include <cuda_bf16.h>
#include <cstdint>
#include <math.h>

#define BB 4
#define NSEQ 2048
#define CDIM 768
#define HH 12
#define DD 64
#define HIDD 3072
#define MROWS (BB * NSEQ)   // 8192

// ---------------- scratch ----------------
__device__ float g_h[MROWS * CDIM];
__device__ __nv_bfloat16 g_qb[MROWS * CDIM];   // Q bf16 [B,H,N,D], scaled 0.125*log2e
__device__ __nv_bfloat16 g_kb[MROWS * CDIM];   // K bf16 [B,H,N,D]
__device__ float g_v[MROWS * CDIM];            // V fp32 [B,H,D,N] d-major
__device__ __nv_bfloat16 g_vb[MROWS * CDIM];   // V bf16 [B,H,D,N] d-major
__device__ float g_o[MROWS * CDIM];
__device__ float g_x1[MROWS * CDIM];
__device__ float g_hid[MROWS * HIDD];
// tf32-rounded weights
__device__ float g_wqkv[3 * CDIM * CDIM];
__device__ float g_wproj[CDIM * CDIM];
__device__ float g_wfc1[HIDD * CDIM];
__device__ float g_wfc2[CDIM * HIDD];

__device__ __forceinline__ float to_tf32(float x) {
    float y;
    asm("cvt.rna.tf32.f32 %0, %1;" : "=f"(y) : "f"(x));
    return y;
}
__device__ __forceinline__ float ex2(float x) {
    float y;
    asm("ex2.approx.ftz.f32 %0, %1;" : "=f"(y) : "f"(x));
    return y;
}
__device__ __forceinline__ uint32_t smem_u32(const void* p) {
    uint32_t a;
    asm("{ .reg .u64 t; cvta.to.shared.u64 t, %1; cvt.u32.u64 %0, t; }" : "=r"(a) : "l"(p));
    return a;
}
__device__ __forceinline__ void mma_tf32(float* d, const uint32_t* a, const uint32_t* b) {
    asm volatile(
        "mma.sync.aligned.m16n8k8.row.col.f32.tf32.tf32.f32 "
        "{%0,%1,%2,%3}, {%4,%5,%6,%7}, {%8,%9}, {%0,%1,%2,%3};"
        : "+f"(d[0]), "+f"(d[1]), "+f"(d[2]), "+f"(d[3])
        : "r"(a[0]), "r"(a[1]), "r"(a[2]), "r"(a[3]), "r"(b[0]), "r"(b[1]));
}
__device__ __forceinline__ void mma_bf16(float* d, const uint32_t* a, uint32_t b0, uint32_t b1) {
    asm volatile(
        "mma.sync.aligned.m16n8k16.row.col.f32.bf16.bf16.f32 "
        "{%0,%1,%2,%3}, {%4,%5,%6,%7}, {%8,%9}, {%0,%1,%2,%3};"
        : "+f"(d[0]), "+f"(d[1]), "+f"(d[2]), "+f"(d[3])
        : "r"(a[0]), "r"(a[1]), "r"(a[2]), "r"(a[3]), "r"(b0), "r"(b1));
}
__device__ __forceinline__ void ldsm4(uint32_t* r, uint32_t addr) {
    asm volatile("ldmatrix.sync.aligned.m8n8.x4.shared.b16 {%0,%1,%2,%3}, [%4];"
                 : "=r"(r[0]), "=r"(r[1]), "=r"(r[2]), "=r"(r[3]) : "r"(addr));
}
__device__ __forceinline__ void cp16(uint32_t dst, const void* src) {
    asm volatile("cp.async.cg.shared.global [%0], [%1], 16;"
                 :: "r"(dst), "l"(__cvta_generic_to_global(src)));
}
#define CP_COMMIT() asm volatile("cp.async.commit_group;" ::: "memory")
#define CP_WAIT1()  asm volatile("cp.async.wait_group 1;" ::: "memory")
#define CP_WAIT0()  asm volatile("cp.async.wait_group 0;" ::: "memory")

__device__ __forceinline__ uint32_t pack_bf16(float a, float b) {
    __nv_bfloat162 h = __floats2bfloat162_rn(a, b);
    return *(uint32_t*)&h;
}

// ---------------- weight tf32 pre-round ----------------
__global__ __launch_bounds__(256) void wcvt_kernel(
    const float* s0, float* d0, int n0, const float* s1, float* d1, int n1,
    const float* s2, float* d2, int n2, const float* s3, float* d3, int n3) {
    const float* s; float* d; int n;
    switch (blockIdx.y) {
        case 0: s = s0; d = d0; n = n0; break;
        case 1: s = s1; d = d1; n = n1; break;
        case 2: s = s2; d = d2; n = n2; break;
        default: s = s3; d = d3; n = n3; break;
    }
    int i = (blockIdx.x * 256 + threadIdx.x) * 4;
    if (i < n) {
        float4 v = *(const float4*)(s + i);
        v.x = to_tf32(v.x); v.y = to_tf32(v.y); v.z = to_tf32(v.z); v.w = to_tf32(v.w);
        *(float4*)(d + i) = v;
    }
}

// ---------------- V fp32 -> bf16 ----------------
__global__ __launch_bounds__(256) void vcvt_kernel(const float* __restrict__ v,
                                                   __nv_bfloat16* __restrict__ vb) {
    size_t i = ((size_t)blockIdx.x * 256 + threadIdx.x) * 4;
    float4 a = *(const float4*)(v + i);
    uint2 o;
    o.x = pack_bf16(a.x, a.y);
    o.y = pack_bf16(a.z, a.w);
    *(uint2*)(vb + i) = o;
}

// ---------------- cp.async tensor-core GEMM: C = A[M,K] * W[Nn,K]^T ----------------
#define GS 3
#define STG_B 32768
#define GEMM_SMEM (GS * STG_B)

template <int EPI>
__global__ __launch_bounds__(256, 2) void gemm_cp(
    const float* __restrict__ A, const float* __restrict__ W,
    const float* __restrict__ bias, const float* __restrict__ res,
    float* __restrict__ C, int M, int Nn, int K,
    __nv_bfloat16* __restrict__ qout, __nv_bfloat16* __restrict__ kout,
    float* __restrict__ vout) {
    extern __shared__ char sm[];
    uint32_t sb = smem_u32(sm);
    int tid = threadIdx.x, lane = tid & 31, wid = tid >> 5;
    int warpM = wid & 1, warpN = wid >> 1;
    int g = lane >> 2, t = lane & 3;
    int rowBase = blockIdx.y * 128, colBase = blockIdx.x * 128;

    float acc[4][4][4];
#pragma unroll
    for (int i = 0; i < 4; i++)
#pragma unroll
        for (int j = 0; j < 4; j++)
#pragma unroll
            for (int e = 0; e < 4; e++) acc[i][j][e] = 0.f;

    const int r0 = tid >> 3;
    const int c16 = tid & 7;
    const uint32_t csw = (uint32_t)((c16 ^ (r0 & 7)) << 4);
    const float* Ab = A + (size_t)rowBase * K + c16 * 4;
    const float* Wb = W + (size_t)colBase * K + c16 * 4;

    const int r7 = lane & 7;
    const int hiA = lane >> 4;
    const int hiB = (lane >> 3) & 1;
    uint32_t rbA[4], rbB[2];
#pragma unroll
    for (int mt = 0; mt < 4; mt++)
        rbA[mt] = (uint32_t)((warpM * 64 + mt * 16 + (lane & 15)) * 128);
#pragma unroll
    for (int p = 0; p < 2; p++)
        rbB[p] = (uint32_t)((warpN * 32 + p * 16 + (lane & 7) + ((lane >> 4) << 3)) * 128) + 16384;

    const int nc = K >> 5;
#pragma unroll
    for (int s = 0; s < GS - 1; s++) {
        uint32_t sA = sb + s * STG_B;
        const float* Ac = Ab + s * 32;
        const float* Wc = Wb + s * 32;
#pragma unroll
        for (int i = 0; i < 4; i++) {
            int r = r0 + i * 32;
            cp16(sA + r * 128 + csw, Ac + (size_t)r * K);
            cp16(sA + 16384 + r * 128 + csw, Wc + (size_t)r * K);
        }
        CP_COMMIT();
    }

    for (int c = 0; c < nc; c++) {
        CP_WAIT1();
        __syncthreads();
        int nxt = c + GS - 1;
        if (nxt < nc) {
            uint32_t sA = sb + (nxt % GS) * STG_B;
            const float* Ac = Ab + nxt * 32;
            const float* Wc = Wb + nxt * 32;
#pragma unroll
            for (int i = 0; i < 4; i++) {
                int r = r0 + i * 32;
                cp16(sA + r * 128 + csw, Ac + (size_t)r * K);
                cp16(sA + 16384 + r * 128 + csw, Wc + (size_t)r * K);
            }
        }
        CP_COMMIT();
        uint32_t stg = sb + (c % GS) * STG_B;
#pragma unroll
        for (int ks = 0; ks < 4; ks++) {
            uint32_t colA = (uint32_t)((((2 * ks + hiA) ^ r7)) << 4);
            uint32_t colB = (uint32_t)((((2 * ks + hiB) ^ r7)) << 4);
            uint32_t af[4][4], bf[2][4];
#pragma unroll
            for (int mt = 0; mt < 4; mt++) ldsm4(af[mt], stg + rbA[mt] + colA);
#pragma unroll
            for (int p = 0; p < 2; p++) ldsm4(bf[p], stg + rbB[p] + colB);
#pragma unroll
            for (int mt = 0; mt < 4; mt++)
#pragma unroll
                for (int nt = 0; nt < 4; nt++)
                    mma_tf32(acc[mt][nt], af[mt], &bf[nt >> 1][(nt & 1) * 2]);
        }
    }

#pragma unroll
    for (int mt = 0; mt < 4; mt++) {
        int rlo = rowBase + warpM * 64 + mt * 16 + g;
#pragma unroll
        for (int nt = 0; nt < 4; nt++) {
            int colb = colBase + warpN * 32 + nt * 8 + t * 2;
#pragma unroll
            for (int half = 0; half < 2; half++) {
                int row = rlo + half * 8;
                float v0 = acc[mt][nt][half * 2 + 0];
                float v1 = acc[mt][nt][half * 2 + 1];
                if (EPI == 0) {
                    int which = colb / CDIM;
                    int rem = colb - which * CDIM;
                    int h = rem >> 6, d0 = rem & 63;
                    int bq = row >> 11, n = row & 2047;
                    if (which == 2) {
                        float* dst = vout + (((size_t)bq * HH + h) * DD + d0) * NSEQ + n;
                        dst[0] = v0;
                        dst[NSEQ] = v1;
                    } else {
                        // q scaled by 0.125*log2(e) for exp2 softmax; k unscaled
                        float scale = (which == 0) ? 0.18033688f : 1.0f;
                        __nv_bfloat16* dst = (which == 0 ? qout : kout) +
                                             ((((size_t)bq * HH + h) * NSEQ + n) * DD + d0);
                        *(uint32_t*)dst = pack_bf16(v0 * scale, v1 * scale);
                    }
                } else if (EPI == 1) {
                    float2 bv = *(const float2*)(bias + colb);
                    float2 rv = *(const float2*)(res + (size_t)row * Nn + colb);
                    *(float2*)(C + (size_t)row * Nn + colb) =
                        make_float2(v0 + bv.x + rv.x, v1 + bv.y + rv.y);
                } else {
                    float2 bv = *(const float2*)(bias + colb);
                    float u0 = v0 + bv.x, u1 = v1 + bv.y;
                    float2 o;
                    o.x = to_tf32(0.5f * u0 * (1.0f + erff(u0 * 0.70710678f)));
                    o.y = to_tf32(0.5f * u1 * (1.0f + erff(u1 * 0.70710678f)));
                    *(float2*)(C + (size_t)row * Nn + colb) = o;
                }
            }
        }
    }
}

// ---------------- LayerNorm (tf32-rounded output) ----------------
__global__ __launch_bounds__(256) void ln_kernel(const float* __restrict__ X,
                                                 const float* __restrict__ gam,
                                                 const float* __restrict__ bet,
                                                 float* __restrict__ out) {
    int row = blockIdx.x;
    const float* xr = X + (size_t)row * CDIM;
    float v[3];
    float s = 0.f, s2 = 0.f;
#pragma unroll
    for (int i = 0; i < 3; i++) {
        v[i] = xr[threadIdx.x + i * 256];
        s += v[i];
        s2 += v[i] * v[i];
    }
#pragma unroll
    for (int o = 16; o > 0; o >>= 1) {
        s  += __shfl_xor_sync(0xffffffffu, s, o);
        s2 += __shfl_xor_sync(0xffffffffu, s2, o);
    }
    __shared__ float ws[8], ws2[8];
    int wid = threadIdx.x >> 5, lane = threadIdx.x & 31;
    if (lane == 0) { ws[wid] = s; ws2[wid] = s2; }
    __syncthreads();
    if (wid == 0) {
        s  = (lane < 8) ? ws[lane] : 0.f;
        s2 = (lane < 8) ? ws2[lane] : 0.f;
#pragma unroll
        for (int o = 4; o > 0; o >>= 1) {
            s  += __shfl_xor_sync(0xffffffffu, s, o);
            s2 += __shfl_xor_sync(0xffffffffu, s2, o);
        }
        if (lane == 0) { ws[0] = s; ws2[0] = s2; }
    }
    __syncthreads();
    float mu   = ws[0] * (1.0f / CDIM);
    float var  = ws2[0] * (1.0f / CDIM) - mu * mu;
    float rstd = rsqrtf(var + 1e-5f);
#pragma unroll
    for (int i = 0; i < 3; i++) {
        int c = threadIdx.x + i * 256;
        out[(size_t)row * CDIM + c] = to_tf32((v[i] - mu) * rstd * gam[c] + bet[c]);
    }
}

// ---------------- Flash attention: bf16 MMA, P in regs, K+V both cp.async bf16 ----------------
#define OFF_KB 0
#define OFF_VB 16384
#define ATT_SMEM 32768

__global__ __launch_bounds__(256, 2) void attn_mma(const __nv_bfloat16* __restrict__ Q,
                                                   const __nv_bfloat16* __restrict__ K,
                                                   const __nv_bfloat16* __restrict__ V,
                                                   float* __restrict__ O) {
    extern __shared__ float smf[];
    uint32_t sbase = smem_u32(smf);
    int tid = threadIdx.x, lane = tid & 31, wm = tid >> 5;
    int g = lane >> 2, t = lane & 3;
    int bh = blockIdx.y;
    int b = bh / HH, h = bh - b * HH;
    int qbase = blockIdx.x * 128;

    const __nv_bfloat16* Kbase = K + (size_t)bh * NSEQ * DD;
    const __nv_bfloat16* Vbase = V + (size_t)bh * DD * NSEQ;   // bf16 d-major

    // Q A-frags (bf16), resident for whole kernel
    uint32_t qf[4][4];
    {
        const __nv_bfloat16* Qg = Q + ((size_t)bh * NSEQ + qbase + wm * 16) * DD;
#pragma unroll
        for (int ks = 0; ks < 4; ks++) {
            qf[ks][0] = *(const uint32_t*)(Qg + (size_t)g * DD + ks * 16 + 2 * t);
            qf[ks][1] = *(const uint32_t*)(Qg + (size_t)(g + 8) * DD + ks * 16 + 2 * t);
            qf[ks][2] = *(const uint32_t*)(Qg + (size_t)g * DD + ks * 16 + 2 * t + 8);
            qf[ks][3] = *(const uint32_t*)(Qg + (size_t)(g + 8) * DD + ks * 16 + 2 * t + 8);
        }
    }

    float acc_o[8][4];
#pragma unroll
    for (int i = 0; i < 8; i++)
#pragma unroll
        for (int j = 0; j < 4; j++) acc_o[i][j] = 0.f;
    float m0r = -1e30f, m1r = -1e30f, l0 = 0.f, l1 = 0.f;

    const int l15 = lane & 15, l7 = lane & 7, hi = lane >> 4;
    const int str = tid >> 3;       // rows str, str+32
    const int stc = tid & 7;
    const uint32_t stsw = (uint32_t)((stc ^ (str & 7)) << 4);

    // prologue: cp.async K+V tile 0 into buffer 0
#pragma unroll
    for (int i = 0; i < 2; i++) {
        int r = str + i * 32;
        cp16(sbase + OFF_KB + r * 128 + stsw, Kbase + (size_t)r * DD + stc * 8);
        cp16(sbase + OFF_VB + r * 128 + stsw, Vbase + (size_t)r * NSEQ + stc * 8);
    }
    CP_COMMIT();

    for (int kt = 0; kt < NSEQ / 64; kt++) {
        int buf = kt & 1;
        CP_WAIT0();
        __syncthreads();
        if (kt + 1 < NSEQ / 64) {
            int nb = buf ^ 1;
#pragma unroll
            for (int i = 0; i < 2; i++) {
                int r = str + i * 32;
                cp16(sbase + OFF_KB + nb * 8192 + r * 128 + stsw,
                     Kbase + (size_t)(kt * 64 + 64 + r) * DD + stc * 8);
                cp16(sbase + OFF_VB + nb * 8192 + r * 128 + stsw,
                     Vbase + (size_t)r * NSEQ + (kt * 64 + 64) + stc * 8);
            }
        }
        CP_COMMIT();

        const uint32_t kB = sbase + OFF_KB + buf * 8192;
        const uint32_t vB = sbase + OFF_VB + buf * 8192;

        // S = Q K^T  (bf16 m16n8k16): 4 ks x 8 nt
        float s[8][4];
#pragma unroll
        for (int i = 0; i < 8; i++)
#pragma unroll
            for (int j = 0; j < 4; j++) s[i][j] = 0.f;
#pragma unroll
        for (int ks = 0; ks < 4; ks++) {
            uint32_t csw = (uint32_t)(((ks * 2 + hi) ^ l7) << 4);
            uint32_t kb[4][4];
#pragma unroll
            for (int p = 0; p < 4; p++)
                ldsm4(kb[p], kB + (p * 16 + l15) * 128 + csw);
#pragma unroll
            for (int p = 0; p < 4; p++) {
                mma_bf16(s[2 * p + 0], qf[ks], kb[p][0], kb[p][2]);
                mma_bf16(s[2 * p + 1], qf[ks], kb[p][1], kb[p][3]);
            }
        }

        // online softmax (base-2, MUFU ex2); P A-frags built in registers
        float mx0 = -1e30f, mx1 = -1e30f;
#pragma unroll
        for (int nt = 0; nt < 8; nt++) {
            mx0 = fmaxf(mx0, fmaxf(s[nt][0], s[nt][1]));
            mx1 = fmaxf(mx1, fmaxf(s[nt][2], s[nt][3]));
        }
        mx0 = fmaxf(mx0, __shfl_xor_sync(0xffffffffu, mx0, 1));
        mx0 = fmaxf(mx0, __shfl_xor_sync(0xffffffffu, mx0, 2));
        mx1 = fmaxf(mx1, __shfl_xor_sync(0xffffffffu, mx1, 1));
        mx1 = fmaxf(mx1, __shfl_xor_sync(0xffffffffu, mx1, 2));
        float nm0 = fmaxf(m0r, mx0), nm1 = fmaxf(m1r, mx1);
        float al0 = ex2(m0r - nm0), al1 = ex2(m1r - nm1);
        float ts0 = 0.f, ts1 = 0.f;
        uint32_t pa[4][4];
#pragma unroll
        for (int nt = 0; nt < 8; nt++) {
            float p00 = ex2(s[nt][0] - nm0);
            float p01 = ex2(s[nt][1] - nm0);
            float p10 = ex2(s[nt][2] - nm1);
            float p11 = ex2(s[nt][3] - nm1);
            ts0 += p00 + p01; ts1 += p10 + p11;
            int kk = nt >> 1, hf = (nt & 1) * 2;
            pa[kk][hf + 0] = pack_bf16(p00, p01);
            pa[kk][hf + 1] = pack_bf16(p10, p11);
        }
        ts0 += __shfl_xor_sync(0xffffffffu, ts0, 1);
        ts0 += __shfl_xor_sync(0xffffffffu, ts0, 2);
        ts1 += __shfl_xor_sync(0xffffffffu, ts1, 1);
        ts1 += __shfl_xor_sync(0xffffffffu, ts1, 2);
        l0 = l0 * al0 + ts0;
        l1 = l1 * al1 + ts1;
        m0r = nm0; m1r = nm1;
#pragma unroll
        for (int nt = 0; nt < 8; nt++) {
            acc_o[nt][0] *= al0; acc_o[nt][1] *= al0;
            acc_o[nt][2] *= al1; acc_o[nt][3] *= al1;
        }

        // O += P V  (bf16): P A-frags from registers
#pragma unroll
        for (int kk = 0; kk < 4; kk++) {
            uint32_t csw = (uint32_t)(((kk * 2 + hi) ^ l7) << 4);
#pragma unroll
            for (int p = 0; p < 4; p++) {
                uint32_t vb[4];
                ldsm4(vb, vB + (p * 16 + l15) * 128 + csw);
                mma_bf16(acc_o[2 * p + 0], pa[kk], vb[0], vb[2]);
                mma_bf16(acc_o[2 * p + 1], pa[kk], vb[1], vb[3]);
            }
        }
    }

    float inv0 = 1.0f / l0, inv1 = 1.0f / l1;
    int row0 = qbase + wm * 16 + g;
    float* Ob = O + ((size_t)b * NSEQ) * CDIM + h * DD;
#pragma unroll
    for (int nt = 0; nt < 8; nt++) {
        int col = nt * 8 + 2 * t;
        *(float2*)(Ob + (size_t)row0 * CDIM + col) =
            make_float2(to_tf32(acc_o[nt][0] * inv0), to_tf32(acc_o[nt][1] * inv0));
        *(float2*)(Ob + (size_t)(row0 + 8) * CDIM + col) =
            make_float2(to_tf32(acc_o[nt][2] * inv1), to_tf32(acc_o[nt][3] * inv1));
    }
}

// ---------------- host ----------------
extern "C" void kernel_launch(void* const* d_in, const int* in_sizes, int n_in,
                              void* d_out, int out_size) {
    const float* x      = (const float*)d_in[0];
    const float* ln1_g  = (const float*)d_in[1];
    const float* ln1_b  = (const float*)d_in[2];
    const float* qkv_w  = (const float*)d_in[3];
    const float* proj_w = (const float*)d_in[4];
    const float* proj_b = (const float*)d_in[5];
    const float* ln2_g  = (const float*)d_in[6];
    const float* ln2_b  = (const float*)d_in[7];
    const float* fc1_w  = (const float*)d_in[8];
    const float* fc1_b  = (const float*)d_in[9];
    const float* fc2_w  = (const float*)d_in[10];
    const float* fc2_b  = (const float*)d_in[11];
    float* out = (float*)d_out;

    float *h, *v, *o, *x1, *hid, *wqkv, *wproj, *wfc1, *wfc2;
    __nv_bfloat16 *qb, *kb, *vb;
    cudaGetSymbolAddress((void**)&h,    g_h);
    cudaGetSymbolAddress((void**)&qb,   g_qb);
    cudaGetSymbolAddress((void**)&kb,   g_kb);
    cudaGetSymbolAddress((void**)&v,    g_v);
    cudaGetSymbolAddress((void**)&vb,   g_vb);
    cudaGetSymbolAddress((void**)&o,    g_o);
    cudaGetSymbolAddress((void**)&x1,   g_x1);
    cudaGetSymbolAddress((void**)&hid,  g_hid);
    cudaGetSymbolAddress((void**)&wqkv, g_wqkv);
    cudaGetSymbolAddress((void**)&wproj, g_wproj);
    cudaGetSymbolAddress((void**)&wfc1, g_wfc1);
    cudaGetSymbolAddress((void**)&wfc2, g_wfc2);

    cudaFuncSetAttribute(attn_mma, cudaFuncAttributeMaxDynamicSharedMemorySize, ATT_SMEM);
    cudaFuncSetAttribute(gemm_cp<0>, cudaFuncAttributeMaxDynamicSharedMemorySize, GEMM_SMEM);
    cudaFuncSetAttribute(gemm_cp<1>, cudaFuncAttributeMaxDynamicSharedMemorySize, GEMM_SMEM);
    cudaFuncSetAttribute(gemm_cp<2>, cudaFuncAttributeMaxDynamicSharedMemorySize, GEMM_SMEM);

    int nmax = HIDD * CDIM;
    wcvt_kernel<<<dim3((nmax / 4 + 255) / 256, 4), 256>>>(
        qkv_w, wqkv, 3 * CDIM * CDIM, proj_w, wproj, CDIM * CDIM,
        fc1_w, wfc1, HIDD * CDIM, fc2_w, wfc2, CDIM * HIDD);
    ln_kernel<<<MROWS, 256>>>(x, ln1_g, ln1_b, h);
    gemm_cp<0><<<dim3(3 * CDIM / 128, MROWS / 128), 256, GEMM_SMEM>>>(
        h, wqkv, nullptr, nullptr, nullptr, MROWS, 3 * CDIM, CDIM, qb, kb, v);
    vcvt_kernel<<<(MROWS * CDIM / 4) / 256, 256>>>(v, vb);
    attn_mma<<<dim3(NSEQ / 128, BB * HH), 256, ATT_SMEM>>>(qb, kb, vb, o);
    gemm_cp<1><<<dim3(CDIM / 128, MROWS / 128), 256, GEMM_SMEM>>>(
        o, wproj, proj_b, x, x1, MROWS, CDIM, CDIM, nullptr, nullptr, nullptr);
    ln_kernel<<<MROWS, 256>>>(x1, ln2_g, ln2_b, h);
    gemm_cp<2><<<dim3(HIDD / 128, MROWS / 128), 256, GEMM_SMEM>>>(
        h, wfc1, fc1_b, nullptr, hid, MROWS, HIDD, CDIM, nullptr, nullptr, nullptr);
    gemm_cp<1><<<dim3(CDIM / 128, MROWS / 128), 256, GEMM_SMEM>>>(
        hid, wfc2, fc2_b, x1, out, MROWS, CDIM, HIDD, nullptr, nullptr, nullptr);
}